// round 1
// baseline (speedup 1.0000x reference)
#include <cuda_runtime.h>

#define BATCH 16384
#define INSZ  64

typedef unsigned long long u64;
typedef unsigned int       u32;

// Scratch (device globals: allocation-free rule)
__device__ float g_xT[INSZ * BATCH];   // x transposed: [i][b]
__device__ float g_hT[INSZ * BATCH];   // layer0 output transposed: [o][b]

__device__ __forceinline__ u64 fma2(u64 a, u64 b, u64 c) {
    u64 d;
    asm("fma.rn.f32x2 %0, %1, %2, %3;" : "=l"(d) : "l"(a), "l"(b), "l"(c));
    return d;
}

__device__ __forceinline__ u64 relu2(u64 v) {
    float lo = __uint_as_float((u32)v);
    float hi = __uint_as_float((u32)(v >> 32));
    lo = fmaxf(lo, 0.0f);
    hi = fmaxf(hi, 0.0f);
    return (u64)__float_as_uint(lo) | ((u64)__float_as_uint(hi) << 32);
}

// Transpose x [BATCH][INSZ] -> g_xT [INSZ][BATCH]
__global__ void transpose_x(const float* __restrict__ x) {
    __shared__ float t[32][33];
    int tx = threadIdx.x, ty = threadIdx.y;
    int b0 = blockIdx.x * 32, i0 = blockIdx.y * 32;
#pragma unroll
    for (int k = 0; k < 32; k += 8)
        t[ty + k][tx] = x[(size_t)(b0 + ty + k) * INSZ + i0 + tx];
    __syncthreads();
#pragma unroll
    for (int k = 0; k < 32; k += 8)
        g_xT[(size_t)(i0 + ty + k) * BATCH + b0 + tx] = t[tx][ty + k];
}

// One KAN layer. MODE 0: read g_xT, write g_hT transposed ([o][b]).
//                MODE 1: read g_hT, write dout in [b][o] layout.
// CTA: 256 threads = 8 warps; warp w handles output column o = o0 + w for
// 64 batch elements (32 lanes x 2 packed). Params staged in smem duplicated
// as (w,w) pairs so fma.rn.f32x2 needs zero splat MOVs in the inner loop.
template <int OUT, int MODE>
__global__ __launch_bounds__(256, 4) void kan_layer(
    const float* __restrict__ W1, const float* __restrict__ b1,
    const float* __restrict__ W2, const float* __restrict__ b2,
    const float* __restrict__ W3, const float* __restrict__ b3,
    float* __restrict__ dout)
{
    constexpr int OTILE = 8;
    __shared__ float sp[INSZ * OTILE * 24];   // 48KB exactly

    const float* xT = (MODE == 0) ? g_xT : g_hT;
    int tid = threadIdx.x;
    int o0  = blockIdx.y * OTILE;

    // Stage duplicated params: entry s = i*8 + ol  ->  subnet n = i*OUT + o0 + ol
    for (int s = tid; s < INSZ * OTILE; s += 256) {
        int i  = s >> 3;
        int ol = s & 7;
        int n  = i * OUT + o0 + ol;
        float* e = sp + s * 24;
        float a;
        a = W1[2 * n];     e[0]  = a; e[1]  = a;   // w1a
        a = W1[2 * n + 1]; e[2]  = a; e[3]  = a;   // w1b
        a = b1[2 * n];     e[4]  = a; e[5]  = a;   // b1a
        a = b1[2 * n + 1]; e[6]  = a; e[7]  = a;   // b1b
        a = W2[4 * n];     e[8]  = a; e[9]  = a;   // w2[0][0]
        a = W2[4 * n + 1]; e[10] = a; e[11] = a;   // w2[0][1]
        a = W2[4 * n + 2]; e[12] = a; e[13] = a;   // w2[1][0]
        a = W2[4 * n + 3]; e[14] = a; e[15] = a;   // w2[1][1]
        a = b2[2 * n];     e[16] = a; e[17] = a;   // b2a
        a = b2[2 * n + 1]; e[18] = a; e[19] = a;   // b2b
        a = W3[2 * n];     e[20] = a; e[21] = a;   // w3a
        a = W3[2 * n + 1]; e[22] = a; e[23] = a;   // w3b
    }

    int lane = tid & 31;
    int ol   = tid >> 5;
    int o    = o0 + ol;

    // Per-o sum of b3 over all 64 inputs (folded into accumulator init)
    float s3 = b3[lane * OUT + o] + b3[(lane + 32) * OUT + o];
#pragma unroll
    for (int m = 16; m; m >>= 1) s3 += __shfl_xor_sync(0xffffffffu, s3, m);

    __syncthreads();

    int b0 = blockIdx.x * 64 + lane * 2;
    u64 acc0 = (u64)__float_as_uint(s3) | ((u64)__float_as_uint(s3) << 32);
    u64 acc1 = 0;   // (0.f, 0.f)

    const ulonglong2* pp = ((const ulonglong2*)sp) + ol * 6;
    const float* xb = xT + b0;

#pragma unroll 2
    for (int i = 0; i < INSZ; i++) {
        u64 xv = *(const u64*)(xb + (size_t)i * BATCH);
        const ulonglong2* e = pp + i * (OTILE * 6);
        ulonglong2 e0 = e[0], e1 = e[1], e2 = e[2], e3 = e[3], e4 = e[4], e5 = e[5];
        // h1 = relu(W1*x + b1)
        u64 r1 = relu2(fma2(e0.x, xv, e1.x));
        u64 r2 = relu2(fma2(e0.y, xv, e1.y));
        // h2 = relu(W2 @ h1 + b2)
        u64 ga = relu2(fma2(e2.x, r1, fma2(e2.y, r2, e4.x)));
        u64 gb = relu2(fma2(e3.x, r1, fma2(e3.y, r2, e4.y)));
        // acc += W3 . h2
        acc0 = fma2(e5.x, ga, acc0);
        acc1 = fma2(e5.y, gb, acc1);
    }

    float a_lo = __uint_as_float((u32)acc0) + __uint_as_float((u32)acc1);
    float a_hi = __uint_as_float((u32)(acc0 >> 32)) + __uint_as_float((u32)(acc1 >> 32));

    if (MODE == 0) {
        u64 r = (u64)__float_as_uint(a_lo) | ((u64)__float_as_uint(a_hi) << 32);
        *(u64*)(g_hT + (size_t)o * BATCH + b0) = r;     // transposed, coalesced STG.64
    } else {
        dout[(size_t)b0 * OUT + o]       = a_lo;
        dout[(size_t)(b0 + 1) * OUT + o] = a_hi;
    }
}

extern "C" void kernel_launch(void* const* d_in, const int* in_sizes, int n_in,
                              void* d_out, int out_size)
{
    const float* x    = (const float*)d_in[0];
    const float* l0W1 = (const float*)d_in[1];
    const float* l0b1 = (const float*)d_in[2];
    const float* l0W2 = (const float*)d_in[3];
    const float* l0b2 = (const float*)d_in[4];
    const float* l0W3 = (const float*)d_in[5];
    const float* l0b3 = (const float*)d_in[6];
    const float* l1W1 = (const float*)d_in[7];
    const float* l1b1 = (const float*)d_in[8];
    const float* l1W2 = (const float*)d_in[9];
    const float* l1b2 = (const float*)d_in[10];
    const float* l1W3 = (const float*)d_in[11];
    const float* l1b3 = (const float*)d_in[12];
    float* out = (float*)d_out;

    transpose_x<<<dim3(BATCH / 32, INSZ / 32), dim3(32, 8)>>>(x);
    kan_layer<64, 0><<<dim3(BATCH / 64, 64 / 8), 256>>>(l0W1, l0b1, l0W2, l0b2,
                                                        l0W3, l0b3, nullptr);
    kan_layer<16, 1><<<dim3(BATCH / 64, 16 / 8), 256>>>(l1W1, l1b1, l1W2, l1b2,
                                                        l1W3, l1b3, out);
}